// round 17
// baseline (speedup 1.0000x reference)
#include <cuda_runtime.h>
#include <cuda_bf16.h>
#include <math.h>

#define NN   50000
#define EE   600000
#define D    128
#define OUTD 64
#define NBLK ((NN + 255) / 256)

// ---------------- scratch (device globals; no allocation) ----------------
__device__ int      g_is64;
__device__ int      g_cnt[NN];
__device__ int      g_part[NBLK];
__device__ int      g_off[NN + 1];
__device__ int      g_fill[NN + 1];
__device__ int      g_csr_src[EE];
__device__ float    g_h   [(size_t)NN * D];
__device__ float    g_bufA[(size_t)NN * D];
__device__ float    g_si[NN];
__device__ float    g_sj[NN];
__device__ float    g_Wc[D * OUTD];
__device__ float    g_bc[OUTD];
// per layer: [kc 0..15][nf 0..15][lane 0..31] pair=(W[8kc+tc][8nf+g], W[8kc+tc+4][8nf+g]) raw fp32 bits
__device__ uint2    g_Wt[3 * 8192];

// ---------------- detect dtype + zero histogram ----------------
__global__ void k_detect(const void* ei) {
    int i = blockIdx.x * 256 + threadIdx.x;
    if (i < NN) g_cnt[i] = 0;
    if (blockIdx.x == 0 && threadIdx.x < 32) {
        const long long* p = (const long long*)ei;
        long long v = p[threadIdx.x];
        int bad = (v < 0 || v >= NN) ? 1 : 0;
        unsigned b = __ballot_sync(0xffffffffu, bad);
        if (threadIdx.x == 0) g_is64 = (b == 0) ? 1 : 0;
    }
}

// ---------------- histogram: 4 edges/thread ----------------
__global__ void k_hist(const void* ei) {
    int i0 = (blockIdx.x * blockDim.x + threadIdx.x) * 4;
    if (i0 >= EE) return;
    int is64 = g_is64;
    int d[4];
    if (is64) {
        const long long* p = (const long long*)ei + EE;
#pragma unroll
        for (int q = 0; q < 4; q++) d[q] = (int)p[i0 + q];
    } else {
        const int* p = (const int*)ei + EE;
#pragma unroll
        for (int q = 0; q < 4; q++) d[q] = p[i0 + q];
    }
#pragma unroll
    for (int q = 0; q < 4; q++) atomicAdd(&g_cnt[d[q]], 1);
}

__device__ __forceinline__ void mma8(float* c, unsigned a0, unsigned a1, unsigned a2, unsigned a3,
                                     unsigned b0, unsigned b1) {
    asm volatile("mma.sync.aligned.m16n8k8.row.col.f32.tf32.tf32.f32 "
                 "{%0,%1,%2,%3}, {%4,%5,%6,%7}, {%8,%9}, {%0,%1,%2,%3};"
                 : "+f"(c[0]), "+f"(c[1]), "+f"(c[2]), "+f"(c[3])
                 : "r"(a0), "r"(a1), "r"(a2), "r"(a3), "r"(b0), "r"(b1));
}

// ---------------- W -> fragment-ready layout (raw bits, no cvt) ----------------
__global__ void k_cvtW(const float* __restrict__ Ws) {
    int idx = blockIdx.x * 256 + threadIdx.x;
    if (idx >= 3 * 8192) return;
    int l    = idx >> 13;
    int rem  = idx & 8191;
    int kc   = rem >> 9;
    int r2   = rem & 511;
    int nf   = r2 >> 5;
    int lane = r2 & 31;
    int tc = lane & 3, g = lane >> 2;
    const float* W = Ws + (size_t)l * D * D;
    int n = nf * 8 + g;
    unsigned w0 = __float_as_uint(W[(kc * 8 + tc) * D + n]);
    unsigned w1 = __float_as_uint(W[(kc * 8 + tc + 4) * D + n]);
    g_Wt[idx] = make_uint2(w0, w1);
}

// ---------------- scan ----------------
__global__ void k_scanA() {
    __shared__ int sw[8];
    int b = blockIdx.x;
    int i = b * 256 + threadIdx.x;
    int v = (i < NN) ? g_cnt[i] : 0;
    int lane = threadIdx.x & 31, wid = threadIdx.x >> 5;
#pragma unroll
    for (int o = 16; o > 0; o >>= 1) v += __shfl_xor_sync(0xffffffffu, v, o);
    if (lane == 0) sw[wid] = v;
    __syncthreads();
    if (threadIdx.x == 0) {
        int s = 0;
#pragma unroll
        for (int w = 0; w < 8; w++) s += sw[w];
        g_part[b] = s;
    }
}

__global__ void k_scanC() {
    __shared__ int sw[8];
    __shared__ int sbase;
    int b = blockIdx.x;
    int i = b * 256 + threadIdx.x;
    int lane = threadIdx.x & 31, wid = threadIdx.x >> 5;
    int v = (i < NN) ? g_cnt[i] : 0;
    int x = v;
#pragma unroll
    for (int o = 1; o < 32; o <<= 1) {
        int t = __shfl_up_sync(0xffffffffu, x, o);
        if (lane >= o) x += t;
    }
    if (lane == 31) sw[wid] = x;
    if (wid == 1) {
        int s = 0;
        for (int j = lane; j < b; j += 32) s += g_part[j];
#pragma unroll
        for (int o = 16; o > 0; o >>= 1) s += __shfl_xor_sync(0xffffffffu, s, o);
        if (lane == 0) sbase = s;
    }
    __syncthreads();
    if (wid == 0 && lane < 8) {
        int y = sw[lane];
#pragma unroll
        for (int o = 1; o < 8; o <<= 1) {
            int t = __shfl_up_sync(0xffu, y, o);
            if (lane >= o) y += t;
        }
        sw[lane] = y;
    }
    __syncthreads();
    int incl = x + (wid ? sw[wid - 1] : 0) + sbase;
    if (i < NN) { g_off[i + 1] = incl; g_fill[i + 1] = incl; }
    if (i == 0) { g_off[0] = 0; g_fill[0] = 0; }
}

// ---------------- reorder: 4 edges/thread ----------------
__global__ void k_reorder(const void* ei) {
    int i0 = (blockIdx.x * blockDim.x + threadIdx.x) * 4;
    if (i0 >= EE) return;
    int is64 = g_is64;
    int s[4], d[4];
    if (is64) {
        const long long* ps = (const long long*)ei;
        const long long* pd = ps + EE;
#pragma unroll
        for (int q = 0; q < 4; q++) { s[q] = (int)ps[i0 + q]; d[q] = (int)pd[i0 + q]; }
    } else {
        const int* ps = (const int*)ei;
        const int* pd = ps + EE;
#pragma unroll
        for (int q = 0; q < 4; q++) { s[q] = ps[i0 + q]; d[q] = pd[i0 + q]; }
    }
    int pos[4];
#pragma unroll
    for (int q = 0; q < 4; q++) pos[q] = atomicAdd(&g_fill[d[q]], 1);
#pragma unroll
    for (int q = 0; q < 4; q++) g_csr_src[pos[q]] = s[q];
}

// ---------------- GEMM: 128x128 tile, 4 warps (2m x 2n), mf=4, raw-tf32 ----------------
__global__ void __launch_bounds__(128)
k_gemm(const float* __restrict__ X, const uint2* __restrict__ Wt,
       const float* __restrict__ bias, const float* __restrict__ att,
       float* __restrict__ Y, int nrows) {
    __shared__ uint2 Ap[2][128][6];   // [row][tc] pair=(A[r][tc], A[r][tc+4]) raw bits; 48B row stride
    __shared__ uint2 Bf[2][16][32];   // fragment-ready: [nf][lane]
    __shared__ float sSi[128][2], sSj[128][2];

    int t = threadIdx.x;
    int lane = t & 31, wid = t >> 5;
    int warp_m = wid >> 1, warp_n = wid & 1;
    int g = lane >> 2, tc = lane & 3;
    int row0 = blockIdx.x * 128;

    float c[4][8][4];
#pragma unroll
    for (int mf = 0; mf < 4; mf++)
#pragma unroll
        for (int nf = 0; nf < 8; nf++)
#pragma unroll
            for (int q = 0; q < 4; q++) c[mf][nf][q] = 0.f;

    float4 ax, ay;
    uint4 bx0, bx1;

    // ---- prologue: load + store chunk 0 ----
    {
        int gr = row0 + t;
        ax = make_float4(0.f, 0.f, 0.f, 0.f); ay = ax;
        if (gr < nrows) {
            ax = *(const float4*)&X[(size_t)gr * D + 0];
            ay = *(const float4*)&X[(size_t)gr * D + 4];
        }
        const uint2* src = Wt + t * 4;           // chunk 0: 512 uint2
        bx0 = *(const uint4*)(src + 0);
        bx1 = *(const uint4*)(src + 2);
    }
    {
        *(uint4*)&Ap[0][t][0] = make_uint4(__float_as_uint(ax.x), __float_as_uint(ay.x),
                                           __float_as_uint(ax.y), __float_as_uint(ay.y));
        *(uint4*)&Ap[0][t][2] = make_uint4(__float_as_uint(ax.z), __float_as_uint(ay.z),
                                           __float_as_uint(ax.w), __float_as_uint(ay.w));
        uint2* bd = &Bf[0][0][0] + t * 4;
        *(uint4*)(bd + 0) = bx0;
        *(uint4*)(bd + 2) = bx1;
    }
    __syncthreads();

    for (int kt = 0; kt < 16; kt++) {
        int cur = kt & 1;
        if (kt < 15) {
            int gr = row0 + t;
            ax = make_float4(0.f, 0.f, 0.f, 0.f); ay = ax;
            if (gr < nrows) {
                ax = *(const float4*)&X[(size_t)gr * D + (kt + 1) * 8 + 0];
                ay = *(const float4*)&X[(size_t)gr * D + (kt + 1) * 8 + 4];
            }
            const uint2* src = Wt + (kt + 1) * 512 + t * 4;
            bx0 = *(const uint4*)(src + 0);
            bx1 = *(const uint4*)(src + 2);
        }
        // ---- MMA on cur ----
        unsigned a[4][4];
#pragma unroll
        for (int mf = 0; mf < 4; mf++) {
            int r = warp_m * 64 + mf * 16 + g;
            uint2 p0 = Ap[cur][r][tc];
            uint2 p1 = Ap[cur][r + 8][tc];
            a[mf][0] = p0.x; a[mf][1] = p1.x; a[mf][2] = p0.y; a[mf][3] = p1.y;
        }
#pragma unroll
        for (int nf = 0; nf < 8; nf++) {
            uint2 b = Bf[cur][warp_n * 8 + nf][lane];
#pragma unroll
            for (int mf = 0; mf < 4; mf++)
                mma8(c[mf][nf], a[mf][0], a[mf][1], a[mf][2], a[mf][3], b.x, b.y);
        }
        if (kt < 15) {
            int nxt = 1 - cur;
            *(uint4*)&Ap[nxt][t][0] = make_uint4(__float_as_uint(ax.x), __float_as_uint(ay.x),
                                                 __float_as_uint(ax.y), __float_as_uint(ay.y));
            *(uint4*)&Ap[nxt][t][2] = make_uint4(__float_as_uint(ax.z), __float_as_uint(ay.z),
                                                 __float_as_uint(ax.w), __float_as_uint(ay.w));
            uint2* bd = &Bf[nxt][0][0] + t * 4;
            *(uint4*)(bd + 0) = bx0;
            *(uint4*)(bd + 2) = bx1;
            __syncthreads();
        }
    }

    // ---- epilogue: bias add, Y store, si/sj reduction ----
#pragma unroll
    for (int mf = 0; mf < 4; mf++) {
        int rA = warp_m * 64 + mf * 16 + g;
        int rB = rA + 8;
        int grA = row0 + rA, grB = row0 + rB;
        float siA = 0.f, sjA = 0.f, siB = 0.f, sjB = 0.f;
#pragma unroll
        for (int nf = 0; nf < 8; nf++) {
            int col = warp_n * 64 + nf * 8 + tc * 2;
            float b0 = bias[col], b1 = bias[col + 1];
            float z0 = c[mf][nf][0] + b0, z1 = c[mf][nf][1] + b1;
            float z2 = c[mf][nf][2] + b0, z3 = c[mf][nf][3] + b1;
            if (grA < nrows) *(float2*)&Y[(size_t)grA * D + col] = make_float2(z0, z1);
            if (grB < nrows) *(float2*)&Y[(size_t)grB * D + col] = make_float2(z2, z3);
            float ai0 = att[col], ai1 = att[col + 1];
            float aj0 = att[D + col], aj1 = att[D + col + 1];
            siA = fmaf(z0, ai0, fmaf(z1, ai1, siA));
            sjA = fmaf(z0, aj0, fmaf(z1, aj1, sjA));
            siB = fmaf(z2, ai0, fmaf(z3, ai1, siB));
            sjB = fmaf(z2, aj0, fmaf(z3, aj1, sjB));
        }
#pragma unroll
        for (int o = 1; o < 4; o <<= 1) {
            siA += __shfl_xor_sync(0xffffffffu, siA, o);
            sjA += __shfl_xor_sync(0xffffffffu, sjA, o);
            siB += __shfl_xor_sync(0xffffffffu, siB, o);
            sjB += __shfl_xor_sync(0xffffffffu, sjB, o);
        }
        if (tc == 0) {
            sSi[rA][warp_n] = siA; sSj[rA][warp_n] = sjA;
            sSi[rB][warp_n] = siB; sSj[rB][warp_n] = sjB;
        }
    }
    __syncthreads();
    {
        int gr = row0 + t;
        if (gr < nrows) {
            g_si[gr] = sSi[t][0] + sSi[t][1];
            g_sj[gr] = sSj[t][0] + sSj[t][1];
        }
    }
}

// ---------------- fused edge kernel (unchanged) ----------------
#define WPB 8
__global__ void k_edge(const float* __restrict__ h, const float* __restrict__ bias,
                       float* __restrict__ out) {
    __shared__ float sAlpha[WPB][64];
    __shared__ int   sSrc[WPB][64];
    int wi = threadIdx.x >> 5;
    int node = blockIdx.x * WPB + wi;
    int lane = threadIdx.x & 31;
    int beg = g_off[node], end = g_off[node + 1];
    int deg = end - beg;
    float si_n = g_si[node];
    float4 acc = make_float4(0.f, 0.f, 0.f, 0.f);

    if (deg > 0 && deg <= 64) {
        float m = -1e30f, sum = 0.f;
        for (int i = lane; i < deg; i += 32) {
            int s = g_csr_src[beg + i];
            float v = si_n + g_sj[s];
            float e = v > 0.f ? v : 0.2f * v;
            sSrc[wi][i] = s;
            sAlpha[wi][i] = e;
            float mn = fmaxf(m, e);
            sum = sum * __expf(m - mn) + __expf(e - mn);
            m = mn;
        }
#pragma unroll
        for (int o = 16; o > 0; o >>= 1) {
            float mo = __shfl_xor_sync(0xffffffffu, m, o);
            float so = __shfl_xor_sync(0xffffffffu, sum, o);
            float mn = fmaxf(m, mo);
            sum = sum * __expf(m - mn) + so * __expf(mo - mn);
            m = mn;
        }
        float inv = 1.f / (sum + 1e-16f);
        for (int i = lane; i < deg; i += 32)
            sAlpha[wi][i] = __expf(sAlpha[wi][i] - m) * inv;
        __syncwarp();

        int i = 0;
        for (; i + 8 <= deg; i += 8) {
            float4 hv[8]; float a[8];
#pragma unroll
            for (int j = 0; j < 8; j++) {
                a[j]  = sAlpha[wi][i + j];
                hv[j] = ((const float4*)h)[(size_t)sSrc[wi][i + j] * 32 + lane];
            }
#pragma unroll
            for (int j = 0; j < 8; j++) {
                acc.x = fmaf(a[j], hv[j].x, acc.x);
                acc.y = fmaf(a[j], hv[j].y, acc.y);
                acc.z = fmaf(a[j], hv[j].z, acc.z);
                acc.w = fmaf(a[j], hv[j].w, acc.w);
            }
        }
        for (; i < deg; i++) {
            float a = sAlpha[wi][i];
            float4 hv = ((const float4*)h)[(size_t)sSrc[wi][i] * 32 + lane];
            acc.x = fmaf(a, hv.x, acc.x);
            acc.y = fmaf(a, hv.y, acc.y);
            acc.z = fmaf(a, hv.z, acc.z);
            acc.w = fmaf(a, hv.w, acc.w);
        }
    } else if (deg > 64) {
        float m = -1e30f, sum = 0.f;
        for (int i = beg + lane; i < end; i += 32) {
            int s = g_csr_src[i];
            float v = si_n + g_sj[s];
            float e = v > 0.f ? v : 0.2f * v;
            float mn = fmaxf(m, e);
            sum = sum * __expf(m - mn) + __expf(e - mn);
            m = mn;
        }
#pragma unroll
        for (int o = 16; o > 0; o >>= 1) {
            float mo = __shfl_xor_sync(0xffffffffu, m, o);
            float so = __shfl_xor_sync(0xffffffffu, sum, o);
            float mn = fmaxf(m, mo);
            sum = sum * __expf(m - mn) + so * __expf(mo - mn);
            m = mn;
        }
        float inv = 1.f / (sum + 1e-16f);

        for (int base = beg; base < end; base += 64) {
            int cnt = min(64, end - base);
            for (int i = lane; i < cnt; i += 32) {
                int s = g_csr_src[base + i];
                float v = si_n + g_sj[s];
                float e = v > 0.f ? v : 0.2f * v;
                sAlpha[wi][i] = __expf(e - m) * inv;
                sSrc[wi][i] = s;
            }
            __syncwarp();
            int i = 0;
            for (; i + 8 <= cnt; i += 8) {
                float4 hv[8]; float a[8];
#pragma unroll
                for (int j = 0; j < 8; j++) {
                    a[j]  = sAlpha[wi][i + j];
                    hv[j] = ((const float4*)h)[(size_t)sSrc[wi][i + j] * 32 + lane];
                }
#pragma unroll
                for (int j = 0; j < 8; j++) {
                    acc.x = fmaf(a[j], hv[j].x, acc.x);
                    acc.y = fmaf(a[j], hv[j].y, acc.y);
                    acc.z = fmaf(a[j], hv[j].z, acc.z);
                    acc.w = fmaf(a[j], hv[j].w, acc.w);
                }
            }
            for (; i < cnt; i++) {
                float a = sAlpha[wi][i];
                float4 hv = ((const float4*)h)[(size_t)sSrc[wi][i] * 32 + lane];
                acc.x = fmaf(a, hv.x, acc.x);
                acc.y = fmaf(a, hv.y, acc.y);
                acc.z = fmaf(a, hv.z, acc.z);
                acc.w = fmaf(a, hv.w, acc.w);
            }
            __syncwarp();
        }
    }

    float4 b4 = ((const float4*)bias)[lane];
    float4 o4;
    o4.x = fmaxf(acc.x + b4.x, 0.f);
    o4.y = fmaxf(acc.y + b4.y, 0.f);
    o4.z = fmaxf(acc.z + b4.z, 0.f);
    o4.w = fmaxf(acc.w + b4.w, 0.f);
    ((float4*)out)[(size_t)node * 32 + lane] = o4;
}

// ---------------- combine final MLP ----------------
__global__ void k_combine(const float* __restrict__ Wp1, const float* __restrict__ bp1,
                          const float* __restrict__ Wp2, const float* __restrict__ bp2) {
    int c = blockIdx.x;
    int k = threadIdx.x;
    float s = 0.f;
    for (int mm = 0; mm < D; mm++) s = fmaf(Wp1[k * D + mm], Wp2[mm * OUTD + c], s);
    g_Wc[k * OUTD + c] = s;
    if (k == 0) {
        float b = bp2[c];
        for (int mm = 0; mm < D; mm++) b = fmaf(bp1[mm], Wp2[mm * OUTD + c], b);
        g_bc[c] = b;
    }
}

// ---------------- final GEMM + log_softmax ----------------
__global__ void __launch_bounds__(256, 4)
k_final(const float* __restrict__ x3, const float* __restrict__ Wc,
        const float* __restrict__ bc, float* __restrict__ out) {
    __shared__ float Xs[32][68];
    __shared__ float Ws[32][68];
    int t = threadIdx.x;
    int row0 = blockIdx.x * 64;
    int tx = t & 15, ty = t >> 4;
    float acc[4][4];
#pragma unroll
    for (int i = 0; i < 4; i++)
#pragma unroll
        for (int j = 0; j < 4; j++) acc[i][j] = 0.f;

    for (int kt = 0; kt < 4; kt++) {
#pragma unroll
        for (int l = 0; l < 2; l++) {
            int idx = t + l * 256;
            int r = idx >> 3;
            int kq = (idx & 7) * 4;
            int gr = row0 + r;
            float4 v = make_float4(0.f, 0.f, 0.f, 0.f);
            if (gr < NN) v = *(const float4*)&x3[(size_t)gr * D + kt * 32 + kq];
            Xs[kq + 0][r] = v.x; Xs[kq + 1][r] = v.y;
            Xs[kq + 2][r] = v.z; Xs[kq + 3][r] = v.w;
        }
#pragma unroll
        for (int l = 0; l < 2; l++) {
            int idx = t + l * 256;
            int r = idx >> 4;
            int cq = (idx & 15) * 4;
            *(float4*)&Ws[r][cq] = *(const float4*)&Wc[(size_t)(kt * 32 + r) * OUTD + cq];
        }
        __syncthreads();
#pragma unroll
        for (int kk = 0; kk < 32; kk++) {
            float4 av = *(float4*)&Xs[kk][ty * 4];
            float4 wv = *(float4*)&Ws[kk][tx * 4];
            float a[4] = {av.x, av.y, av.z, av.w};
            float w[4] = {wv.x, wv.y, wv.z, wv.w};
#pragma unroll
            for (int i = 0; i < 4; i++)
#pragma unroll
                for (int j = 0; j < 4; j++)
                    acc[i][j] = fmaf(a[i], w[j], acc[i][j]);
        }
        __syncthreads();
    }

    float b[4];
#pragma unroll
    for (int j = 0; j < 4; j++) b[j] = bc[tx * 4 + j];
#pragma unroll
    for (int i = 0; i < 4; i++) {
        float z[4];
        float m = -1e30f;
#pragma unroll
        for (int j = 0; j < 4; j++) { z[j] = acc[i][j] + b[j]; m = fmaxf(m, z[j]); }
#pragma unroll
        for (int o = 1; o < 16; o <<= 1) m = fmaxf(m, __shfl_xor_sync(0xffffffffu, m, o));
        float s = 0.f;
#pragma unroll
        for (int j = 0; j < 4; j++) s += __expf(z[j] - m);
#pragma unroll
        for (int o = 1; o < 16; o <<= 1) s += __shfl_xor_sync(0xffffffffu, s, o);
        float lg = m + __logf(s);
        int gr = row0 + ty * 4 + i;
        if (gr < NN) {
            float4 o4 = make_float4(z[0] - lg, z[1] - lg, z[2] - lg, z[3] - lg);
            *(float4*)&out[(size_t)gr * OUTD + tx * 4] = o4;
        }
    }
}

// ---------------- host launcher ----------------
extern "C" void kernel_launch(void* const* d_in, const int* in_sizes, int n_in,
                              void* d_out, int out_size) {
    const float* x      = (const float*)d_in[0];
    const void*  ei     = d_in[1];
    const float* Ws     = (const float*)d_in[2];
    const float* bs     = (const float*)d_in[3];
    const float* atts   = (const float*)d_in[4];
    const float* biases = (const float*)d_in[5];
    const float* Wp1    = (const float*)d_in[6];
    const float* bp1    = (const float*)d_in[7];
    const float* Wp2    = (const float*)d_in[8];
    const float* bp2    = (const float*)d_in[9];
    float* out = (float*)d_out;

    float *h, *bufA, *Wc, *bc;
    uint2* Wt;
    void* tmp;
    cudaGetSymbolAddress(&tmp, g_h);    h    = (float*)tmp;
    cudaGetSymbolAddress(&tmp, g_bufA); bufA = (float*)tmp;
    cudaGetSymbolAddress(&tmp, g_Wc);   Wc   = (float*)tmp;
    cudaGetSymbolAddress(&tmp, g_bc);   bc   = (float*)tmp;
    cudaGetSymbolAddress(&tmp, g_Wt);   Wt   = (uint2*)tmp;

    // launch order: 0 detect, 1 hist, 2 cvtW, 3 gemm(l0) <- ncu slot
    k_detect<<<NBLK, 256>>>(ei);
    k_hist<<<(EE / 4 + 255) / 256, 256>>>(ei);
    k_cvtW<<<96, 256>>>(Ws);
    k_gemm<<<(NN + 127) / 128, 128>>>(x, Wt, bs, atts, h, NN);   // layer-0 GEMM
    k_scanA<<<NBLK, 256>>>();
    k_scanC<<<NBLK, 256>>>();
    k_reorder<<<(EE / 4 + 255) / 256, 256>>>(ei);
    k_combine<<<OUTD, D>>>(Wp1, bp1, Wp2, bp2);

    for (int l = 0; l < 3; l++) {
        if (l > 0)
            k_gemm<<<(NN + 127) / 128, 128>>>(bufA, Wt + (size_t)l * 8192, bs + l * D,
                                              atts + (size_t)l * 2 * D, h, NN);
        k_edge<<<NN / WPB, WPB * 32>>>(h, biases + l * D, bufA);
    }
    k_final<<<(NN + 63) / 64, 256>>>(bufA, Wc, bc, out);
}